// round 9
// baseline (speedup 1.0000x reference)
#include <cuda_runtime.h>

// ---------------------------------------------------------------------------
// RNN_57208964382771: Elman RNN (tanh), B=64, T=2048, H=8, V=O=1000
// Fused persistent kernel, ONE BLOCK PER SM (grid = 148):
//   blocks [0, 16)     : recurrence. 4 live warps/block => ONE warp per SMSP.
//       step = 8-FFMA chain (arrival-ordered) + tanh.approx + 8 shfl
//       hs stores buffered 4 steps -> one coalesced 128B STG.32 / 4 steps
//   blocks [16, 148)   : projection over (chunk,batch) tiles, c-major.
//       masked rows (t >= len) stored immediately (bias only)
//       live rows spin on progress flag (tid0, ld.acquire) then W_out·h+b_out
// ---------------------------------------------------------------------------

#define HH     8
#define MAX_B  64
#define MAX_T  2048
#define MAX_V  1000
#define CH     64
#define WPB    4            // recurrence warps per block -> 1 per SMSP
#define GRID   148

__device__ float g_hs[(size_t)MAX_B * MAX_T * HH];
__device__ int   g_progress[MAX_B];

__device__ __forceinline__ float fast_tanh(float x)
{
    float y;
    asm("tanh.approx.f32 %0, %1;" : "=f"(y) : "f"(x));
    return y;
}

__device__ __forceinline__ int load_acquire_gpu(const int* p)
{
    int v;
    asm volatile("ld.acquire.gpu.global.s32 %0, [%1];" : "=r"(v) : "l"(p) : "memory");
    return v;
}

__device__ __forceinline__ void store_cs(float* p, float4 v)
{
    asm volatile("st.global.cs.v4.f32 [%0], {%1,%2,%3,%4};"
                 :: "l"(p), "f"(v.x), "f"(v.y), "f"(v.z), "f"(v.w) : "memory");
}

extern __shared__ char dsmem[];

__global__ void __launch_bounds__(256, 1)
rnn_fused_kernel(const void* __restrict__ Xv,
                 const void* __restrict__ lengthsv,
                 const float* __restrict__ emb,
                 const float* __restrict__ W_ih,
                 const float* __restrict__ W_hh,
                 const float* __restrict__ b_ih,
                 const float* __restrict__ b_hh,
                 const float* __restrict__ W_out,
                 const float* __restrict__ b_out,
                 float* __restrict__ out,
                 int B, int T, int V, int O, int tail, int nrec)
{
    const int bid = blockIdx.x;
    const int tid = threadIdx.x;
    const int nchunk = (T + CH - 1) / CH;

    if (bid < nrec) {
        // =================== recurrence role ===================
        float* s_embproj = (float*)dsmem;                   // V*HH floats
        int*   s_tok     = (int*)(dsmem + MAX_V * HH * 4);  // WPB*(T+2) ints
        __shared__ int s_is64;

        {   // inline dtype detect on X: int64 (<2^31) => odd words all zero
            const int* x32 = (const int*)Xv;
            const int pairs = min(1024, (B * T) >> 1);
            int nz = 0;
            for (int i = tid; i < pairs; i += blockDim.x)
                nz |= (x32[2 * i + 1] != 0);
            const int any = __syncthreads_or(nz);
            if (tid == 0) s_is64 = !any;
            __syncthreads();
        }
        const int is64 = s_is64;

        // --- tokens for this block's WPB batches (all 256 threads help) ---
        const int b0     = bid * WPB;
        const int nbatch = min(WPB, B - b0);
        const int TOT    = nbatch * T;
        if (is64) {
            const long long* X = (const long long*)Xv;
            for (int k = tid; k < TOT; k += blockDim.x) {
                const int wq = k / T, t = k - wq * T;
                int v = (int)X[(long long)(b0 + wq) * T + t];
                s_tok[wq * (T + 2) + t] = min(max(v, 0), V - 1);
            }
        } else {
            const int* X = (const int*)Xv;
            for (int k = tid; k < TOT; k += blockDim.x) {
                const int wq = k / T, t = k - wq * T;
                int v = X[(b0 + wq) * T + t];
                s_tok[wq * (T + 2) + t] = min(max(v, 0), V - 1);
            }
        }
        if (tid < 2 * WPB) s_tok[(tid >> 1) * (T + 2) + T + (tid & 1)] = 0;

        // --- embedding projection with both biases folded in ---
        for (int v = tid; v < V; v += blockDim.x) {
            float e[HH];
#pragma unroll
            for (int h = 0; h < HH; h++) e[h] = emb[v * HH + h];
#pragma unroll
            for (int i = 0; i < HH; i++) {
                float s = b_ih[i] + b_hh[i];
#pragma unroll
                for (int h = 0; h < HH; h++)
                    s = fmaf(e[h], W_ih[i * HH + h], s);
                s_embproj[v * HH + i] = s;
            }
        }
        __syncthreads();

        // ---- ONLY the first WPB warps run the recurrence ----
        if (tid >= WPB * 32) return;
        const int wq    = tid >> 5;
        const int batch = b0 + wq;
        if (batch >= B) return;
        const int lane = tid & 31;
        const int i    = lane & 7;            // lanes 8-31 shadow 0-7
        const int kcap = lane >> 3;           // sub-step this lane captures

        const float w0 = W_hh[i * HH + 0], w1 = W_hh[i * HH + 1];
        const float w2 = W_hh[i * HH + 2], w3 = W_hh[i * HH + 3];
        const float w4 = W_hh[i * HH + 4], w5 = W_hh[i * HH + 5];
        const float w6 = W_hh[i * HH + 6], w7 = W_hh[i * HH + 7];

        float h0 = 0.f, h1 = 0.f, h2 = 0.f, h3 = 0.f;
        float h4 = 0.f, h5 = 0.f, h6 = 0.f, h7 = 0.f;

        float* __restrict__ hs_out = g_hs + (size_t)batch * T * HH;
        const int* __restrict__ tok = s_tok + wq * (T + 2);

        int   tokB = tok[1];
        float xp   = s_embproj[tok[0] * HH + i];

        for (int c = 0; c < nchunk; c++) {
            const int t0 = c * CH;
            const int full = (t0 + CH <= T);
            if (full) {
#pragma unroll 4
                for (int tb = 0; tb < CH; tb += 4) {
                    float ybuf = 0.0f;
#pragma unroll
                    for (int k = 0; k < 4; k++) {
                        const int   t    = t0 + tb + k;
                        const int   tokC = tok[t + 2];
                        const float xp_n = s_embproj[tokB * HH + i];

                        // single chain ordered by shfl-arrival; h7 consumed last
                        float a = fmaf(h0, w0, xp);
                        a = fmaf(h1, w1, a);
                        a = fmaf(h2, w2, a);
                        a = fmaf(h3, w3, a);
                        a = fmaf(h4, w4, a);
                        a = fmaf(h5, w5, a);
                        a = fmaf(h6, w6, a);
                        a = fmaf(h7, w7, a);

                        const float y = fast_tanh(a);
                        if (kcap == k) ybuf = y;     // off-path SEL

                        h0 = __shfl_sync(0xffffffffu, y, 0);
                        h1 = __shfl_sync(0xffffffffu, y, 1);
                        h2 = __shfl_sync(0xffffffffu, y, 2);
                        h3 = __shfl_sync(0xffffffffu, y, 3);
                        h4 = __shfl_sync(0xffffffffu, y, 4);
                        h5 = __shfl_sync(0xffffffffu, y, 5);
                        h6 = __shfl_sync(0xffffffffu, y, 6);
                        h7 = __shfl_sync(0xffffffffu, y, 7);

                        xp   = xp_n;
                        tokB = tokC;
                    }
                    // one coalesced 128B store: steps tb..tb+3, all 8 h each
                    hs_out[(t0 + tb) * HH + lane] = ybuf;
                }
            } else {
                const int tend = min(T, t0 + CH);
                for (int t = t0; t < tend; t++) {
                    const int   tokC = tok[t + 2];
                    const float xp_n = s_embproj[tokB * HH + i];
                    float a = fmaf(h0, w0, xp);
                    a = fmaf(h1, w1, a);
                    a = fmaf(h2, w2, a);
                    a = fmaf(h3, w3, a);
                    a = fmaf(h4, w4, a);
                    a = fmaf(h5, w5, a);
                    a = fmaf(h6, w6, a);
                    a = fmaf(h7, w7, a);
                    const float y = fast_tanh(a);
                    if (lane < HH) hs_out[t * HH + lane] = y;
                    h0 = __shfl_sync(0xffffffffu, y, 0);
                    h1 = __shfl_sync(0xffffffffu, y, 1);
                    h2 = __shfl_sync(0xffffffffu, y, 2);
                    h3 = __shfl_sync(0xffffffffu, y, 3);
                    h4 = __shfl_sync(0xffffffffu, y, 4);
                    h5 = __shfl_sync(0xffffffffu, y, 5);
                    h6 = __shfl_sync(0xffffffffu, y, 6);
                    h7 = __shfl_sync(0xffffffffu, y, 7);
                    xp   = xp_n;
                    tokB = tokC;
                }
            }
            __syncwarp();
            if (lane == 0) {
                __threadfence();
                *(volatile int*)&g_progress[batch] = c + 1;
            }
        }
        return;
    }

    // =================== projection role ===================
    const int p     = bid - nrec;
    const int NPROJ = GRID - nrec;
    const int nvec  = O >> 2;                   // 250

    // lengths dtype: values >= 1, so int32 data has nonzero odd words
    const int* l32 = (const int*)lengthsv;
    int nzl = 0;
    for (int k = 1; k < B; k += 2) nzl |= (l32[k] != 0);
    const int is64l = !nzl;

    if (p == 0 && tail > 0) {
        const long long base = (long long)B * T * O;
        if (tail == 2 * B) {
            if (tid < B) {
                long long lv = is64l ? ((const long long*)lengthsv)[tid]
                                     : (long long)l32[tid];
                ((long long*)(out + base))[tid] = lv;
            }
        } else {
            for (int k = tid; k < tail; k += 256) {
                float v = 0.0f;
                if (k < B)
                    v = (float)(is64l ? ((const long long*)lengthsv)[k]
                                      : (long long)l32[k]);
                out[base + k] = v;
            }
        }
    }

    float w[4][HH];
    float4 bias = make_float4(0.f, 0.f, 0.f, 0.f);
    if (tid < nvec) {
#pragma unroll
        for (int k = 0; k < 4; k++) {
            const int o = tid * 4 + k;
#pragma unroll
            for (int h = 0; h < HH; h++)
                w[k][h] = W_out[o * HH + h];
        }
        bias = *(const float4*)(b_out + tid * 4);
    }

    const int ntiles = B * nchunk;

    // ---- phase 1: fully masked tiles — no dependency, run immediately ----
    for (int tile = p; tile < ntiles; tile += NPROJ) {
        const int c  = tile / B;
        const int b  = tile % B;
        const int t0 = c * CH;
        const int len = is64l ? (int)((const long long*)lengthsv)[b] : l32[b];
        if (len > t0) continue;
        if (tid < nvec) {
            const int rows = min(CH, T - t0);
            float* orow = out + ((size_t)b * T + t0) * O + tid * 4;
            for (int r = 0; r < rows; r++)
                store_cs(orow + (size_t)r * O, bias);
        }
    }

    // ---- phase 2: live tiles, chunk-major (matches production order) ----
    for (int tile = p; tile < ntiles; tile += NPROJ) {
        const int c  = tile / B;
        const int b  = tile % B;
        const int t0 = c * CH;
        const int len = is64l ? (int)((const long long*)lengthsv)[b] : l32[b];
        if (len <= t0) continue;

        if (tid == 0) {
            while (load_acquire_gpu(&g_progress[b]) <= c) __nanosleep(64);
        }
        __syncthreads();

        if (tid < nvec) {
            const int rows = min(CH, T - t0);
            const int rlim = min(rows, len - t0);
            const float* hsrow = g_hs + ((size_t)b * T + t0) * HH;
            float* orow = out + ((size_t)b * T + t0) * O + tid * 4;

            for (int r = 0; r < rlim; r++) {
                const float4 ha = __ldg((const float4*)(hsrow + (size_t)r * HH));
                const float4 hb = __ldg((const float4*)(hsrow + (size_t)r * HH) + 1);
                const float hh[HH] = {ha.x, ha.y, ha.z, ha.w, hb.x, hb.y, hb.z, hb.w};

                float a0 = bias.x, a1 = bias.y, a2 = bias.z, a3 = bias.w;
#pragma unroll
                for (int h = 0; h < HH; h++) {
                    a0 = fmaf(w[0][h], hh[h], a0);
                    a1 = fmaf(w[1][h], hh[h], a1);
                    a2 = fmaf(w[2][h], hh[h], a2);
                    a3 = fmaf(w[3][h], hh[h], a3);
                }
                float4 acc; acc.x = a0; acc.y = a1; acc.z = a2; acc.w = a3;
                store_cs(orow + (size_t)r * O, acc);
            }
            for (int r = rlim; r < rows; r++)
                store_cs(orow + (size_t)r * O, bias);
        }
    }
}

extern "C" void kernel_launch(void* const* d_in, const int* in_sizes, int n_in,
                              void* d_out, int out_size)
{
    const void*  X       = d_in[0];
    const void*  lengths = d_in[1];
    const float* emb     = (const float*)d_in[2];
    const float* W_ih    = (const float*)d_in[3];
    const float* W_hh    = (const float*)d_in[4];
    const float* b_ih    = (const float*)d_in[5];
    const float* b_hh    = (const float*)d_in[6];
    const float* W_out   = (const float*)d_in[7];
    const float* b_out   = (const float*)d_in[8];
    float*       out     = (float*)d_out;

    const int B  = in_sizes[1];
    const int BT = in_sizes[0];
    const int T  = BT / B;
    const int H  = in_sizes[5];
    const int V  = in_sizes[2] / H;
    const int O  = in_sizes[8];

    const long long tail = (long long)out_size - (long long)BT * O;
    const int nrec = (B + WPB - 1) / WPB;          // 16 for B=64

    const int smemBytes = MAX_V * HH * 4 + WPB * (T + 2) * 4;   // ~65 KB
    cudaFuncSetAttribute(rnn_fused_kernel,
                         cudaFuncAttributeMaxDynamicSharedMemorySize,
                         smemBytes);

    void* progAddr = nullptr;
    cudaGetSymbolAddress(&progAddr, g_progress);
    cudaMemsetAsync(progAddr, 0, sizeof(int) * MAX_B);

    rnn_fused_kernel<<<GRID, 256, smemBytes>>>(X, lengths, emb, W_ih, W_hh,
                                               b_ih, b_hh, W_out, b_out, out,
                                               B, T, V, O,
                                               (int)(tail > 0 ? tail : 0), nrec);
}

// round 11
// speedup vs baseline: 1.0202x; 1.0202x over previous
#include <cuda_runtime.h>
#include <cstdint>

// ---------------------------------------------------------------------------
// RNN_57208964382771: Elman RNN (tanh), B=64, T=2048, H=8, V=O=1000
// Fused persistent kernel, ONE BLOCK PER SM (grid = 148):
//   blocks [0, 16)   : recurrence, 4 live warps/block (1 per SMSP).
//     h broadcast via SMEM instead of 8x SHFL:
//       lanes 0-7: STS y -> comm slot k;  all lanes: 2x LDS.128 reload h.
//       Same-warp STS->LDS is in-order through the MIO pipe (no divergence).
//       Every 4 steps: one coalesced 128B STG of the 4-step/8-h tile.
//   blocks [16, 148) : projection over (chunk,batch) tiles (unchanged R8).
// ---------------------------------------------------------------------------

#define HH     8
#define MAX_B  64
#define MAX_T  2048
#define MAX_V  1000
#define CH     64
#define WPB    4            // recurrence warps per block -> 1 per SMSP
#define GRID   148

__device__ float g_hs[(size_t)MAX_B * MAX_T * HH];
__device__ int   g_progress[MAX_B];

__device__ __forceinline__ float fast_tanh(float x)
{
    float y;
    asm("tanh.approx.f32 %0, %1;" : "=f"(y) : "f"(x));
    return y;
}

__device__ __forceinline__ int load_acquire_gpu(const int* p)
{
    int v;
    asm volatile("ld.acquire.gpu.global.s32 %0, [%1];" : "=r"(v) : "l"(p) : "memory");
    return v;
}

__device__ __forceinline__ void store_cs(float* p, float4 v)
{
    asm volatile("st.global.cs.v4.f32 [%0], {%1,%2,%3,%4};"
                 :: "l"(p), "f"(v.x), "f"(v.y), "f"(v.z), "f"(v.w) : "memory");
}

__device__ __forceinline__ unsigned int smem_u32(const void* p)
{
    unsigned int a;
    asm("{ .reg .u64 t; cvta.to.shared.u64 t, %1; cvt.u32.u64 %0, t; }"
        : "=r"(a) : "l"(p));
    return a;
}

__device__ __forceinline__ void sts32(unsigned int addr, float v)
{
    asm volatile("st.shared.f32 [%0], %1;" :: "r"(addr), "f"(v) : "memory");
}

__device__ __forceinline__ float lds32(unsigned int addr)
{
    float v;
    asm volatile("ld.shared.f32 %0, [%1];" : "=f"(v) : "r"(addr) : "memory");
    return v;
}

__device__ __forceinline__ void lds128(unsigned int addr, float& a, float& b, float& c, float& d)
{
    asm volatile("ld.shared.v4.f32 {%0,%1,%2,%3}, [%4];"
                 : "=f"(a), "=f"(b), "=f"(c), "=f"(d) : "r"(addr) : "memory");
}

extern __shared__ char dsmem[];

__global__ void __launch_bounds__(256, 1)
rnn_fused_kernel(const void* __restrict__ Xv,
                 const void* __restrict__ lengthsv,
                 const float* __restrict__ emb,
                 const float* __restrict__ W_ih,
                 const float* __restrict__ W_hh,
                 const float* __restrict__ b_ih,
                 const float* __restrict__ b_hh,
                 const float* __restrict__ W_out,
                 const float* __restrict__ b_out,
                 float* __restrict__ out,
                 int B, int T, int V, int O, int tail, int nrec)
{
    const int bid = blockIdx.x;
    const int tid = threadIdx.x;
    const int nchunk = (T + CH - 1) / CH;

    if (bid < nrec) {
        // =================== recurrence role ===================
        float* s_embproj = (float*)dsmem;                   // V*HH floats
        int*   s_tok     = (int*)(dsmem + MAX_V * HH * 4);  // WPB*(T+2) ints
        __shared__ __align__(16) float s_comm[WPB][32];     // 4 slots x 8 h per warp
        __shared__ int s_is64;

        {   // inline dtype detect on X: int64 (<2^31) => odd words all zero
            const int* x32 = (const int*)Xv;
            const int pairs = min(1024, (B * T) >> 1);
            int nz = 0;
            for (int i = tid; i < pairs; i += blockDim.x)
                nz |= (x32[2 * i + 1] != 0);
            const int any = __syncthreads_or(nz);
            if (tid == 0) s_is64 = !any;
            __syncthreads();
        }
        const int is64 = s_is64;

        // --- tokens for this block's WPB batches (all 256 threads help) ---
        const int b0     = bid * WPB;
        const int nbatch = min(WPB, B - b0);
        const int TOT    = nbatch * T;
        if (is64) {
            const long long* X = (const long long*)Xv;
            for (int k = tid; k < TOT; k += blockDim.x) {
                const int wq = k / T, t = k - wq * T;
                int v = (int)X[(long long)(b0 + wq) * T + t];
                s_tok[wq * (T + 2) + t] = min(max(v, 0), V - 1);
            }
        } else {
            const int* X = (const int*)Xv;
            for (int k = tid; k < TOT; k += blockDim.x) {
                const int wq = k / T, t = k - wq * T;
                int v = X[(b0 + wq) * T + t];
                s_tok[wq * (T + 2) + t] = min(max(v, 0), V - 1);
            }
        }
        if (tid < 2 * WPB) s_tok[(tid >> 1) * (T + 2) + T + (tid & 1)] = 0;

        // --- embedding projection with both biases folded in ---
        for (int v = tid; v < V; v += blockDim.x) {
            float e[HH];
#pragma unroll
            for (int h = 0; h < HH; h++) e[h] = emb[v * HH + h];
#pragma unroll
            for (int i = 0; i < HH; i++) {
                float s = b_ih[i] + b_hh[i];
#pragma unroll
                for (int h = 0; h < HH; h++)
                    s = fmaf(e[h], W_ih[i * HH + h], s);
                s_embproj[v * HH + i] = s;
            }
        }
        __syncthreads();

        // ---- ONLY the first WPB warps run the recurrence ----
        if (tid >= WPB * 32) return;
        const int wq    = tid >> 5;
        const int batch = b0 + wq;
        if (batch >= B) return;
        const int lane = tid & 31;
        const int i    = lane & 7;

        const unsigned int cbase  = smem_u32(&s_comm[wq][0]);
        const unsigned int claneW = cbase + (unsigned int)i * 4u;
        const unsigned int claneR = cbase + (unsigned int)lane * 4u;

        const float w0 = W_hh[i * HH + 0], w1 = W_hh[i * HH + 1];
        const float w2 = W_hh[i * HH + 2], w3 = W_hh[i * HH + 3];
        const float w4 = W_hh[i * HH + 4], w5 = W_hh[i * HH + 5];
        const float w6 = W_hh[i * HH + 6], w7 = W_hh[i * HH + 7];

        float h0 = 0.f, h1 = 0.f, h2 = 0.f, h3 = 0.f;
        float h4 = 0.f, h5 = 0.f, h6 = 0.f, h7 = 0.f;

        float* __restrict__ hs_out = g_hs + (size_t)batch * T * HH;
        const int* __restrict__ tok = s_tok + wq * (T + 2);

        int   tokB = tok[1];
        float xp   = s_embproj[tok[0] * HH + i];

        for (int c = 0; c < nchunk; c++) {
            const int t0 = c * CH;
            const int full = (t0 + CH <= T);
            if (full) {
#pragma unroll 2
                for (int tb = 0; tb < CH; tb += 4) {
#pragma unroll
                    for (int k = 0; k < 4; k++) {
                        const int   t    = t0 + tb + k;
                        const int   tokC = tok[t + 2];
                        const float xp_n = s_embproj[tokB * HH + i];

                        // two 4-FFMA chains + join (R8 structure)
                        float a = fmaf(h0, w0, xp);
                        a = fmaf(h1, w1, a);
                        a = fmaf(h2, w2, a);
                        a = fmaf(h3, w3, a);
                        float bb = h4 * w4;
                        bb = fmaf(h5, w5, bb);
                        bb = fmaf(h6, w6, bb);
                        bb = fmaf(h7, w7, bb);

                        const float y = fast_tanh(a + bb);

                        // SMEM broadcast: lanes 0-7 publish, all lanes reload.
                        // Same-warp STS->LDS: in-order MIO pipe, no sync needed.
                        if (lane < HH) sts32(claneW + (unsigned int)k * 32u, y);
                        lds128(cbase + (unsigned int)k * 32u,       h0, h1, h2, h3);
                        lds128(cbase + (unsigned int)k * 32u + 16u, h4, h5, h6, h7);

                        xp   = xp_n;
                        tokB = tokC;
                    }
                    // coalesced 128B store: 4 steps x 8 h, one STG.32 per lane
                    const float yb = lds32(claneR);
                    hs_out[(t0 + tb) * HH + lane] = yb;
                }
            } else {
                const int tend = min(T, t0 + CH);
                for (int t = t0; t < tend; t++) {
                    const int   tokC = tok[t + 2];
                    const float xp_n = s_embproj[tokB * HH + i];
                    float a = fmaf(h0, w0, xp);
                    a = fmaf(h1, w1, a);
                    a = fmaf(h2, w2, a);
                    a = fmaf(h3, w3, a);
                    float bb = h4 * w4;
                    bb = fmaf(h5, w5, bb);
                    bb = fmaf(h6, w6, bb);
                    bb = fmaf(h7, w7, bb);
                    const float y = fast_tanh(a + bb);
                    if (lane < HH) sts32(claneW, y);
                    lds128(cbase,       h0, h1, h2, h3);
                    lds128(cbase + 16u, h4, h5, h6, h7);
                    if (lane < HH) hs_out[t * HH + lane] = y;
                    xp   = xp_n;
                    tokB = tokC;
                }
            }
            __syncwarp();
            if (lane == 0) {
                __threadfence();
                *(volatile int*)&g_progress[batch] = c + 1;
            }
        }
        return;
    }

    // =================== projection role ===================
    const int p     = bid - nrec;
    const int NPROJ = GRID - nrec;
    const int nvec  = O >> 2;                   // 250

    // lengths dtype: values >= 1, so int32 data has nonzero odd words
    const int* l32 = (const int*)lengthsv;
    int nzl = 0;
    for (int k = 1; k < B; k += 2) nzl |= (l32[k] != 0);
    const int is64l = !nzl;

    if (p == 0 && tail > 0) {
        const long long base = (long long)B * T * O;
        if (tail == 2 * B) {
            if (tid < B) {
                long long lv = is64l ? ((const long long*)lengthsv)[tid]
                                     : (long long)l32[tid];
                ((long long*)(out + base))[tid] = lv;
            }
        } else {
            for (int k = tid; k < tail; k += 256) {
                float v = 0.0f;
                if (k < B)
                    v = (float)(is64l ? ((const long long*)lengthsv)[k]
                                      : (long long)l32[k]);
                out[base + k] = v;
            }
        }
    }

    float w[4][HH];
    float4 bias = make_float4(0.f, 0.f, 0.f, 0.f);
    if (tid < nvec) {
#pragma unroll
        for (int k = 0; k < 4; k++) {
            const int o = tid * 4 + k;
#pragma unroll
            for (int h = 0; h < HH; h++)
                w[k][h] = W_out[o * HH + h];
        }
        bias = *(const float4*)(b_out + tid * 4);
    }

    const int ntiles = B * nchunk;

    // ---- phase 1: fully masked tiles — no dependency, run immediately ----
    for (int tile = p; tile < ntiles; tile += NPROJ) {
        const int c  = tile / B;
        const int b  = tile % B;
        const int t0 = c * CH;
        const int len = is64l ? (int)((const long long*)lengthsv)[b] : l32[b];
        if (len > t0) continue;
        if (tid < nvec) {
            const int rows = min(CH, T - t0);
            float* orow = out + ((size_t)b * T + t0) * O + tid * 4;
            for (int r = 0; r < rows; r++)
                store_cs(orow + (size_t)r * O, bias);
        }
    }

    // ---- phase 2: live tiles, chunk-major (matches production order) ----
    for (int tile = p; tile < ntiles; tile += NPROJ) {
        const int c  = tile / B;
        const int b  = tile % B;
        const int t0 = c * CH;
        const int len = is64l ? (int)((const long long*)lengthsv)[b] : l32[b];
        if (len <= t0) continue;

        if (tid == 0) {
            while (load_acquire_gpu(&g_progress[b]) <= c) __nanosleep(64);
        }
        __syncthreads();

        if (tid < nvec) {
            const int rows = min(CH, T - t0);
            const int rlim = min(rows, len - t0);
            const float* hsrow = g_hs + ((size_t)b * T + t0) * HH;
            float* orow = out + ((size_t)b * T + t0) * O + tid * 4;

            for (int r = 0; r < rlim; r++) {
                const float4 ha = __ldg((const float4*)(hsrow + (size_t)r * HH));
                const float4 hb = __ldg((const float4*)(hsrow + (size_t)r * HH) + 1);
                const float hh[HH] = {ha.x, ha.y, ha.z, ha.w, hb.x, hb.y, hb.z, hb.w};

                float a0 = bias.x, a1 = bias.y, a2 = bias.z, a3 = bias.w;
#pragma unroll
                for (int h = 0; h < HH; h++) {
                    a0 = fmaf(w[0][h], hh[h], a0);
                    a1 = fmaf(w[1][h], hh[h], a1);
                    a2 = fmaf(w[2][h], hh[h], a2);
                    a3 = fmaf(w[3][h], hh[h], a3);
                }
                float4 acc; acc.x = a0; acc.y = a1; acc.z = a2; acc.w = a3;
                store_cs(orow + (size_t)r * O, acc);
            }
            for (int r = rlim; r < rows; r++)
                store_cs(orow + (size_t)r * O, bias);
        }
    }
}

extern "C" void kernel_launch(void* const* d_in, const int* in_sizes, int n_in,
                              void* d_out, int out_size)
{
    const void*  X       = d_in[0];
    const void*  lengths = d_in[1];
    const float* emb     = (const float*)d_in[2];
    const float* W_ih    = (const float*)d_in[3];
    const float* W_hh    = (const float*)d_in[4];
    const float* b_ih    = (const float*)d_in[5];
    const float* b_hh    = (const float*)d_in[6];
    const float* W_out   = (const float*)d_in[7];
    const float* b_out   = (const float*)d_in[8];
    float*       out     = (float*)d_out;

    const int B  = in_sizes[1];
    const int BT = in_sizes[0];
    const int T  = BT / B;
    const int H  = in_sizes[5];
    const int V  = in_sizes[2] / H;
    const int O  = in_sizes[8];

    const long long tail = (long long)out_size - (long long)BT * O;
    const int nrec = (B + WPB - 1) / WPB;          // 16 for B=64

    const int smemBytes = MAX_V * HH * 4 + WPB * (T + 2) * 4;   // ~65 KB
    cudaFuncSetAttribute(rnn_fused_kernel,
                         cudaFuncAttributeMaxDynamicSharedMemorySize,
                         smemBytes);

    void* progAddr = nullptr;
    cudaGetSymbolAddress(&progAddr, g_progress);
    cudaMemsetAsync(progAddr, 0, sizeof(int) * MAX_B);

    rnn_fused_kernel<<<GRID, 256, smemBytes>>>(X, lengths, emb, W_ih, W_hh,
                                               b_ih, b_hh, W_out, b_out, out,
                                               B, T, V, O,
                                               (int)(tail > 0 ? tail : 0), nrec);
}